// round 11
// baseline (speedup 1.0000x reference)
#include <cuda_runtime.h>
#include <cstdint>

// -------------------------------------------------------------------------
// SpecialSpmmFinal: out[n,f] = sum_{e : src[e]==n} edge_w[e,f]
// N=100000, E=3200000, F=16 fp32.
//
// TMA-fed coalesced-atomic scatter:
//   - edge_w + src are staged into SMEM via cp.async.bulk (TMA/UBLKCP),
//     which bypasses L1TEX entirely — leaving the L1TEX wavefront pipe
//     (the measured binder at ~70% across R8-R10) exclusively for the
//     RED.128 atomic stream.
//   - 4-stage mbarrier pipeline, 128 edges (8.5KB) per chunk.
//   - Consumers: 4 lanes per edge each LDS a 16B quarter-row and issue one
//     RED.128 into a contiguous 64B output row (coalesced atomics, as R8).
// -------------------------------------------------------------------------

#define FEAT    16
#define CHUNK   128                 // edges per chunk
#define STAGES  4
#define THREADS 256
#define QR_PER_CHUNK (CHUNK * 4)    // 512 quarter-rows per chunk
#define QR_PER_THREAD (QR_PER_CHUNK / THREADS)  // 2
#define W_BYTES (CHUNK * 64)        // 8192
#define S_BYTES (CHUNK * 4)         // 512

__device__ __forceinline__ uint32_t smem_u32(const void* p) {
    return (uint32_t)__cvta_generic_to_shared(p);
}

__device__ __forceinline__ void red_v4(float* o, float4 v) {
    asm volatile("red.global.add.v4.f32 [%0], {%1,%2,%3,%4};"
                 :: "l"(o), "f"(v.x), "f"(v.y), "f"(v.z), "f"(v.w) : "memory");
}

__device__ __forceinline__ void mbar_wait(uint32_t mbar, uint32_t parity) {
    asm volatile(
        "{\n\t"
        ".reg .pred P;\n\t"
        "WAIT_%=:\n\t"
        "mbarrier.try_wait.parity.acquire.cta.shared::cta.b64 P, [%0], %1, 0x989680;\n\t"
        "@!P bra WAIT_%=;\n\t"
        "}"
        :: "r"(mbar), "r"(parity) : "memory");
}

__device__ __forceinline__ void issue_chunk(uint32_t dst_w, uint32_t dst_s,
                                            const float4* gw, const int* gs,
                                            uint32_t mbar) {
    asm volatile("mbarrier.arrive.expect_tx.shared.b64 _, [%0], %1;"
                 :: "r"(mbar), "r"((uint32_t)(W_BYTES + S_BYTES)) : "memory");
    asm volatile("cp.async.bulk.shared::cta.global.mbarrier::complete_tx::bytes "
                 "[%0], [%1], %2, [%3];"
                 :: "r"(dst_w), "l"(gw), "r"((uint32_t)W_BYTES), "r"(mbar) : "memory");
    asm volatile("cp.async.bulk.shared::cta.global.mbarrier::complete_tx::bytes "
                 "[%0], [%1], %2, [%3];"
                 :: "r"(dst_s), "l"(gs), "r"((uint32_t)S_BYTES), "r"(mbar) : "memory");
}

__global__ __launch_bounds__(THREADS)
void spmm_pipe_kernel(const int* __restrict__ src,
                      const float4* __restrict__ w,     // [E*4] float4
                      float* __restrict__ out,          // [N*16]
                      int nchunks)
{
    __shared__ __align__(128) float4   sw[STAGES][CHUNK * 4];   // 8KB/stage
    __shared__ __align__(16)  int      ssrc[STAGES][CHUNK];     // 512B/stage
    __shared__ __align__(8)   uint64_t mbar[STAGES];

    const int tid = threadIdx.x;

    if (tid == 0) {
        #pragma unroll
        for (int s = 0; s < STAGES; s++)
            asm volatile("mbarrier.init.shared.b64 [%0], 1;"
                         :: "r"(smem_u32(&mbar[s])) : "memory");
        asm volatile("fence.proxy.async.shared::cta;" ::: "memory");
    }
    __syncthreads();

    int rem = nchunks - blockIdx.x;
    int myN = (rem > 0) ? (rem + gridDim.x - 1) / gridDim.x : 0;

    // Prologue: fill up to STAGES stages.
    if (tid == 0) {
        int pro = (myN < STAGES) ? myN : STAGES;
        for (int k = 0; k < pro; k++) {
            long long g = blockIdx.x + (long long)k * gridDim.x;
            issue_chunk(smem_u32(&sw[k][0]), smem_u32(&ssrc[k][0]),
                        w + g * (CHUNK * 4), src + g * CHUNK,
                        smem_u32(&mbar[k]));
        }
    }

    for (int i = 0; i < myN; i++) {
        int st  = i & (STAGES - 1);
        int par = (i >> 2) & 1;               // STAGES == 4
        mbar_wait(smem_u32(&mbar[st]), par);

        // Consume: 4 adjacent lanes share one edge; each owns a 16B quarter.
        #pragma unroll
        for (int t = 0; t < QR_PER_THREAD; t++) {
            int qi = tid + t * THREADS;       // 0..511
            int e  = qi >> 2;
            int q  = qi & 3;
            int s  = ssrc[st][e];             // broadcast across 4 lanes
            float4 v = sw[st][qi];            // LDS.128
            red_v4(out + (size_t)s * FEAT + q * 4, v);
        }

        __syncthreads();                      // stage st fully consumed

        if (tid == 0) {
            int nk = i + STAGES;
            if (nk < myN) {
                long long g = blockIdx.x + (long long)nk * gridDim.x;
                issue_chunk(smem_u32(&sw[st][0]), smem_u32(&ssrc[st][0]),
                            w + g * (CHUNK * 4), src + g * CHUNK,
                            smem_u32(&mbar[st]));
            }
        }
    }
}

// Generic tail scatter (for E not divisible by CHUNK): same as R10 path.
__global__ __launch_bounds__(256)
void spmm_tail_kernel(const int* __restrict__ src,
                      const float4* __restrict__ w,
                      float* __restrict__ out,
                      int qr_base, int qr_total)
{
    int i = qr_base + blockIdx.x * blockDim.x + threadIdx.x;
    if (i < qr_total) {
        int s = __ldg(&src[i >> 2]);
        float4 v = __ldg(&w[i]);
        red_v4(out + (size_t)s * FEAT + (i & 3) * 4, v);
    }
}

extern "C" void kernel_launch(void* const* d_in, const int* in_sizes, int n_in,
                              void* d_out, int out_size) {
    const int*    edge   = (const int*)d_in[0];      // [2, E], row 0 = src
    const float4* edge_w = (const float4*)d_in[1];   // [E, 16] as float4
    float*        out    = (float*)d_out;            // [N, 16] fp32

    const int E = in_sizes[0] / 2;

    // Zero the poisoned output (stream-ordered, graph-capturable).
    cudaMemsetAsync(out, 0, (size_t)out_size * sizeof(float));

    const int nchunks = E / CHUNK;                   // 25000 for E=3.2M
    const int tail    = E % CHUNK;

    if (nchunks > 0) {
        int grid = nchunks < 592 ? nchunks : 592;    // ~4 CTAs/SM
        spmm_pipe_kernel<<<grid, THREADS>>>(edge, edge_w, out, nchunks);
    }
    if (tail > 0) {
        int qr_base  = nchunks * CHUNK * 4;
        int qr_total = E * 4;
        int n        = qr_total - qr_base;
        spmm_tail_kernel<<<(n + 255) / 256, 256>>>(edge, edge_w, out,
                                                   qr_base, qr_total);
    }
}

// round 13
// speedup vs baseline: 1.0685x; 1.0685x over previous
#include <cuda_runtime.h>
#include <cstdint>

// -------------------------------------------------------------------------
// SpecialSpmmFinal: out[n,f] = sum_{e : src[e]==n} edge_w[e,f]
// N=100000, E=3200000, F=16 fp32.
//
// Bulk-reduce scatter: edge_w + src staged into SMEM via cp.async.bulk
// (TMA-in, 4-stage mbarrier ring), then each edge's 64B row is reduced into
// out[src[e]] via cp.reduce.async.bulk.add.f32 — the TMA/bulk engine does
// the RMW at L2. This removes BOTH measured binders of R8-R11:
//   - zero LDG/RED wavefronts through L1TEX
//   - zero LSU-issued atomic lanes (REDG spread ~1.29 cyc/lane was the
//     50us floor: 12.8M lanes / 148 SMs).
// 3.2M bulk ops (1 per edge) replace 12.8M RED.128 lanes.
// -------------------------------------------------------------------------

#define FEAT    16
#define CHUNK   128                 // edges per chunk
#define STAGES  4
#define THREADS 128                 // one bulk-reduce per thread per chunk
#define W_BYTES (CHUNK * 64)        // 8192
#define S_BYTES (CHUNK * 4)         // 512

__device__ __forceinline__ uint32_t smem_u32(const void* p) {
    return (uint32_t)__cvta_generic_to_shared(p);
}

__device__ __forceinline__ void red_v4(float* o, float4 v) {
    asm volatile("red.global.add.v4.f32 [%0], {%1,%2,%3,%4};"
                 :: "l"(o), "f"(v.x), "f"(v.y), "f"(v.z), "f"(v.w) : "memory");
}

__device__ __forceinline__ void mbar_wait(uint32_t mbar, uint32_t parity) {
    asm volatile(
        "{\n\t"
        ".reg .pred P;\n\t"
        "WAIT_%=:\n\t"
        "mbarrier.try_wait.parity.acquire.cta.shared::cta.b64 P, [%0], %1, 0x989680;\n\t"
        "@!P bra WAIT_%=;\n\t"
        "}"
        :: "r"(mbar), "r"(parity) : "memory");
}

__device__ __forceinline__ void issue_chunk(uint32_t dst_w, uint32_t dst_s,
                                            const float4* gw, const int* gs,
                                            uint32_t mbar) {
    asm volatile("mbarrier.arrive.expect_tx.shared.b64 _, [%0], %1;"
                 :: "r"(mbar), "r"((uint32_t)(W_BYTES + S_BYTES)) : "memory");
    asm volatile("cp.async.bulk.shared::cta.global.mbarrier::complete_tx::bytes "
                 "[%0], [%1], %2, [%3];"
                 :: "r"(dst_w), "l"(gw), "r"((uint32_t)W_BYTES), "r"(mbar) : "memory");
    asm volatile("cp.async.bulk.shared::cta.global.mbarrier::complete_tx::bytes "
                 "[%0], [%1], %2, [%3];"
                 :: "r"(dst_s), "l"(gs), "r"((uint32_t)S_BYTES), "r"(mbar) : "memory");
}

__global__ __launch_bounds__(THREADS)
void spmm_bulkred_kernel(const int* __restrict__ src,
                         const float4* __restrict__ w,     // [E*4] float4
                         float* __restrict__ out,          // [N*16]
                         int nchunks)
{
    __shared__ __align__(128) float4   sw[STAGES][CHUNK * 4];   // 8KB/stage
    __shared__ __align__(16)  int      ssrc[STAGES][CHUNK];     // 512B/stage
    __shared__ __align__(8)   uint64_t mbar[STAGES];

    const int tid = threadIdx.x;

    if (tid == 0) {
        #pragma unroll
        for (int s = 0; s < STAGES; s++)
            asm volatile("mbarrier.init.shared.b64 [%0], 1;"
                         :: "r"(smem_u32(&mbar[s])) : "memory");
        asm volatile("fence.proxy.async.shared::cta;" ::: "memory");
    }
    __syncthreads();

    int rem = nchunks - blockIdx.x;
    int myN = (rem > 0) ? (rem + gridDim.x - 1) / gridDim.x : 0;

    // Prologue: load chunks 0..2 into stages 0..2 (iter i refills chunk i+3).
    if (tid == 0) {
        int pro = (myN < STAGES - 1) ? myN : (STAGES - 1);
        for (int k = 0; k < pro; k++) {
            long long g = blockIdx.x + (long long)k * gridDim.x;
            issue_chunk(smem_u32(&sw[k][0]), smem_u32(&ssrc[k][0]),
                        w + g * (CHUNK * 4), src + g * CHUNK,
                        smem_u32(&mbar[k]));
        }
    }

    for (int i = 0; i < myN; i++) {
        int st  = i & (STAGES - 1);
        int par = (i >> 2) & 1;               // STAGES == 4
        mbar_wait(smem_u32(&mbar[st]), par);

        // One bulk reduce per thread: 64B SMEM row -> out[src[e]] (add.f32
        // RMW performed by the bulk engine at L2; no LSU atomic lanes).
        {
            int s = ssrc[st][tid];
            float* o = out + (size_t)s * FEAT;
            uint32_t sp = smem_u32(&sw[st][tid * 4]);
            asm volatile(
                "cp.reduce.async.bulk.global.shared::cta.bulk_group.add.f32 "
                "[%0], [%1], 64;"
                :: "l"(o), "r"(sp) : "memory");
            asm volatile("cp.async.bulk.commit_group;" ::: "memory");
        }

        // Allow 1 newer group pending -> group i-1's SMEM reads are done,
        // so stage (i-1)%4 (refill target below) is free.
        asm volatile("cp.async.bulk.wait_group.read 1;" ::: "memory");
        __syncthreads();

        if (tid == 0) {
            int c = i + STAGES - 1;           // chunk to prefetch
            if (c < myN) {
                int rst = c & (STAGES - 1);   // == (i-1) & 3
                long long g = blockIdx.x + (long long)c * gridDim.x;
                issue_chunk(smem_u32(&sw[rst][0]), smem_u32(&ssrc[rst][0]),
                            w + g * (CHUNK * 4), src + g * CHUNK,
                            smem_u32(&mbar[rst]));
            }
        }
    }

    // Drain all outstanding bulk reduces before exit.
    asm volatile("cp.async.bulk.wait_group 0;" ::: "memory");
}

// Tail scatter for E % CHUNK edges (classic coalesced RED path).
__global__ __launch_bounds__(256)
void spmm_tail_kernel(const int* __restrict__ src,
                      const float4* __restrict__ w,
                      float* __restrict__ out,
                      int qr_base, int qr_total)
{
    int i = qr_base + blockIdx.x * blockDim.x + threadIdx.x;
    if (i < qr_total) {
        int s = __ldg(&src[i >> 2]);
        float4 v = __ldg(&w[i]);
        red_v4(out + (size_t)s * FEAT + (i & 3) * 4, v);
    }
}

extern "C" void kernel_launch(void* const* d_in, const int* in_sizes, int n_in,
                              void* d_out, int out_size) {
    const int*    edge   = (const int*)d_in[0];      // [2, E], row 0 = src
    const float4* edge_w = (const float4*)d_in[1];   // [E, 16] as float4
    float*        out    = (float*)d_out;            // [N, 16] fp32

    const int E = in_sizes[0] / 2;

    // Zero the poisoned output (stream-ordered, graph-capturable).
    cudaMemsetAsync(out, 0, (size_t)out_size * sizeof(float));

    const int nchunks = E / CHUNK;                   // 25000 for E=3.2M
    const int tail    = E % CHUNK;

    if (nchunks > 0) {
        int grid = nchunks < 592 ? nchunks : 592;    // ~4 CTAs/SM
        spmm_bulkred_kernel<<<grid, THREADS>>>(edge, edge_w, out, nchunks);
    }
    if (tail > 0) {
        int qr_base  = nchunks * CHUNK * 4;
        int qr_total = E * 4;
        int n        = qr_total - qr_base;
        spmm_tail_kernel<<<(n + 255) / 256, 256>>>(edge, edge_w, out,
                                                   qr_base, qr_total);
    }
}

// round 14
// speedup vs baseline: 1.1084x; 1.0373x over previous
#include <cuda_runtime.h>
#include <cstdint>

// -------------------------------------------------------------------------
// SpecialSpmmFinal: out[n,f] = sum_{e : src[e]==n} edge_w[e,f]
// N=100000, E=3200000, F=16 fp32.
//
// Converged design: coalesced-atomic scatter (4 threads/edge, 16B quarter-
// rows, x8 ILP) — measured at the LTS data-array cap (~628 MB through L2
// at ~12.2 TB/s ≈ 51 us; invariant across RED/TMA/bulk-reduce designs).
// This round removes the remaining inter-kernel slack via PDL:
//   - zero kernel triggers launch_dependents at entry
//   - scatter launches early (ProgrammaticStreamSerialization), overlaps
//     its input-load phase with the zeroing, and griddepcontrol.wait's
//     before the first atomic touches d_out.
// -------------------------------------------------------------------------

#define FEAT 16
#define UNROLL 8

__device__ __forceinline__ float4 ldg_stream(const float4* p) {
    float4 v;
    asm volatile("ld.global.nc.L1::no_allocate.v4.f32 {%0,%1,%2,%3}, [%4];"
                 : "=f"(v.x), "=f"(v.y), "=f"(v.z), "=f"(v.w) : "l"(p));
    return v;
}

__device__ __forceinline__ void red_v4(float* o, float4 v) {
    asm volatile("red.global.add.v4.f32 [%0], {%1,%2,%3,%4};"
                 :: "l"(o), "f"(v.x), "f"(v.y), "f"(v.z), "f"(v.w) : "memory");
}

// Zero the output; signal dependents immediately so the scatter's load
// phase overlaps with this kernel's execution.
__global__ __launch_bounds__(256)
void zero_out_kernel(float4* __restrict__ out, int n4) {
    asm volatile("griddepcontrol.launch_dependents;");
    int i = blockIdx.x * blockDim.x + threadIdx.x;
    if (i < n4) out[i] = make_float4(0.f, 0.f, 0.f, 0.f);
}

// Exact version: total quarter-rows == gridDim.x * blockDim.x * UNROLL.
__global__ __launch_bounds__(256)
void spmm_scatter_exact_kernel(const int* __restrict__ src,
                               const float4* __restrict__ w,   // [E*4]
                               float* __restrict__ out)        // [N*16]
{
    const int stride = gridDim.x * blockDim.x;
    const int base = blockIdx.x * blockDim.x + threadIdx.x;

    int    s[UNROLL];
    float4 v[UNROLL];

    // Input loads — safe before the dependency wait (zero kernel only
    // writes d_out). 8 independent LDG.128 + 8 src LDGs in flight.
    #pragma unroll
    for (int k = 0; k < UNROLL; k++) {
        int idx = base + k * stride;
        s[k] = __ldg(&src[idx >> 2]);
    }
    #pragma unroll
    for (int k = 0; k < UNROLL; k++) {
        v[k] = ldg_stream(&w[base + k * stride]);
    }

    // Wait for the zero kernel's stores to be visible before any RED.
    asm volatile("griddepcontrol.wait;" ::: "memory");

    // Coalesced vector reductions — 4 adjacent lanes hit one contiguous
    // 64B output row.
    #pragma unroll
    for (int k = 0; k < UNROLL; k++) {
        int idx = base + k * stride;
        red_v4(out + (size_t)s[k] * FEAT + (idx & 3) * 4, v[k]);
    }
}

// Generic fallback (predicated) for any E; launched without PDL
// (griddepcontrol.wait absent -> plain stream ordering applies).
__global__ __launch_bounds__(256)
void spmm_scatter_gen_kernel(const int* __restrict__ src,
                             const float4* __restrict__ w,
                             float* __restrict__ out,
                             int total)
{
    const int stride = gridDim.x * blockDim.x;
    const int base = blockIdx.x * blockDim.x + threadIdx.x;

    #pragma unroll
    for (int k = 0; k < UNROLL; k++) {
        int idx = base + k * stride;
        if (idx < total) {
            int s = __ldg(&src[idx >> 2]);
            float4 v = ldg_stream(&w[idx]);
            red_v4(out + (size_t)s * FEAT + (idx & 3) * 4, v);
        }
    }
}

extern "C" void kernel_launch(void* const* d_in, const int* in_sizes, int n_in,
                              void* d_out, int out_size) {
    const int*    edge   = (const int*)d_in[0];      // [2, E], row 0 = src
    const float4* edge_w = (const float4*)d_in[1];   // [E, 16] as float4
    float*        out    = (float*)d_out;            // [N, 16] fp32

    const int E = in_sizes[0] / 2;

    // Zero the poisoned output (PDL primary).
    {
        int n4 = out_size / 4;
        int blocks = (n4 + 255) / 256;
        zero_out_kernel<<<blocks, 256>>>((float4*)out, n4);
    }

    const long long total = (long long)E * 4;        // quarter-rows
    const int per_blk = 256 * UNROLL;

    if (total % per_blk == 0) {
        int blocks = (int)(total / per_blk);         // E=3.2M -> 6250

        // PDL secondary: allowed to launch while zero_out_kernel runs.
        cudaLaunchConfig_t cfg = {};
        cfg.gridDim  = dim3((unsigned)blocks, 1, 1);
        cfg.blockDim = dim3(256, 1, 1);
        cfg.dynamicSmemBytes = 0;
        cfg.stream = 0;
        cudaLaunchAttribute attr[1];
        attr[0].id = cudaLaunchAttributeProgrammaticStreamSerialization;
        attr[0].val.programmaticStreamSerializationAllowed = 1;
        cfg.attrs = attr;
        cfg.numAttrs = 1;
        cudaError_t err = cudaLaunchKernelEx(&cfg, spmm_scatter_exact_kernel,
                                             edge, edge_w, out);
        if (err != cudaSuccess) {
            // Fallback: plain launch (wait is a no-op without PDL).
            spmm_scatter_exact_kernel<<<blocks, 256>>>(edge, edge_w, out);
        }
    } else {
        long long threads = (total + UNROLL - 1) / UNROLL;
        int blocks = (int)((threads + 255) / 256);
        spmm_scatter_gen_kernel<<<blocks, 256>>>(edge, edge_w, out, (int)total);
    }
}